// round 2
// baseline (speedup 1.0000x reference)
#include <cuda_runtime.h>
#include <cuda_bf16.h>

// Levinson-Durbin, M=24, one row per thread.
// out[row] = [K, a0..a23] where R a = -r1, K = sqrt(E_24).
//
// R1 changes vs R0:
//  - 4-way split accumulators in the inner dot product (breaks the serial
//    FMA chain that dominated the critical path)
//  - reciprocal pipelining: invE computed one iteration ahead so the MUFU
//    latency hides under the next dot product; k = -acc*invE
//  - E update via identity E*(1-k^2) == fmaf(k, acc, E)  (1 FMA, shorter chain)
//  - __launch_bounds__(256,5) to push occupancy 4 -> 5 blocks/SM
//  - removed redundant middle __syncthreads (owner-only smem access)

constexpr int M_ORD = 24;
constexpr int NC    = M_ORD + 1;    // 25
constexpr int TPB   = 256;
constexpr int NV4   = TPB * NC / 4; // 1600 float4 per block

__device__ __forceinline__ float frcp_fast(float x) {
    float y;
    asm("rcp.approx.f32 %0, %1;" : "=f"(y) : "f"(x));
    return y;
}

__global__ __launch_bounds__(TPB, 5)
void levinson_durbin_kernel(const float* __restrict__ r,
                            float* __restrict__ out,
                            int nrows)
{
    __shared__ float sbuf[TPB * NC];   // 25600 B
    const int tid  = threadIdx.x;
    const int row0 = blockIdx.x * TPB;
    const bool full_block = (row0 + TPB) <= nrows;

    float rr[NC];

    if (full_block) {
        // Coalesced vector load: gmem -> smem
        const float4* gin = reinterpret_cast<const float4*>(r + (size_t)row0 * NC);
        float4* s4 = reinterpret_cast<float4*>(sbuf);
        #pragma unroll
        for (int i = tid; i < NV4; i += TPB) s4[i] = gin[i];
        __syncthreads();
        // stride-25 (odd) per-thread reads: bank-conflict-free
        #pragma unroll
        for (int i = 0; i < NC; i++) rr[i] = sbuf[tid * NC + i];
        // no sync needed: from here each thread touches only its own smem row
    } else {
        int row = row0 + tid;
        if (row < nrows) {
            #pragma unroll
            for (int i = 0; i < NC; i++) rr[i] = r[(size_t)row * NC + i];
        } else {
            #pragma unroll
            for (int i = 0; i < NC; i++) rr[i] = (i == 0) ? 1.0f : 0.0f;
        }
    }

    // ---- Levinson-Durbin recursion (fully unrolled, M=24) ----
    float a[M_ORD];
    float E    = rr[0];
    float invE = frcp_fast(E);

    #pragma unroll
    for (int m = 0; m < M_ORD; m++) {
        // 4-way split dot product: acc = rr[m+1] + sum_i a[i]*rr[m-i]
        float s0 = rr[m + 1], s1 = 0.0f, s2 = 0.0f, s3 = 0.0f;
        #pragma unroll
        for (int i = 0; i + 3 < m; i += 4) {
            s0 = fmaf(a[i    ], rr[m - i    ], s0);
            s1 = fmaf(a[i + 1], rr[m - i - 1], s1);
            s2 = fmaf(a[i + 2], rr[m - i - 2], s2);
            s3 = fmaf(a[i + 3], rr[m - i - 3], s3);
        }
        {
            int i = m & ~3;
            if (i     < m) s0 = fmaf(a[i    ], rr[m - i    ], s0);
            if (i + 1 < m) s1 = fmaf(a[i + 1], rr[m - i - 1], s1);
            if (i + 2 < m) s2 = fmaf(a[i + 2], rr[m - i - 2], s2);
        }
        float acc = (s0 + s1) + (s2 + s3);

        // k = -acc / E, with invE precomputed last iteration (MUFU hidden)
        float k = -acc * invE;

        // symmetric in-place update: a_i' = a_i + k * a_{m-1-i}
        #pragma unroll
        for (int i = 0; i < m / 2; i++) {
            float t = a[i];
            float u = a[m - 1 - i];
            a[i]         = fmaf(k, u, t);
            a[m - 1 - i] = fmaf(k, t, u);
        }
        if (m & 1) {
            float t = a[m / 2];
            a[m / 2] = fmaf(k, t, t);
        }
        a[m] = k;

        // E *= (1 - k^2)  ==  E + k*acc   (since k = -acc/E)
        E    = fmaf(k, acc, E);
        invE = frcp_fast(E);   // hides under next iteration's dot
    }
    const float Kv = sqrtf(E);

    if (full_block) {
        // Stage results in own smem row, then coalesced vector store
        sbuf[tid * NC + 0] = Kv;
        #pragma unroll
        for (int i = 0; i < M_ORD; i++) sbuf[tid * NC + 1 + i] = a[i];
        __syncthreads();
        float4* gout = reinterpret_cast<float4*>(out + (size_t)row0 * NC);
        const float4* s4 = reinterpret_cast<const float4*>(sbuf);
        #pragma unroll
        for (int i = tid; i < NV4; i += TPB) gout[i] = s4[i];
    } else {
        int row = row0 + tid;
        if (row < nrows) {
            out[(size_t)row * NC + 0] = Kv;
            #pragma unroll
            for (int i = 0; i < M_ORD; i++)
                out[(size_t)row * NC + 1 + i] = a[i];
        }
    }
}

extern "C" void kernel_launch(void* const* d_in, const int* in_sizes, int n_in,
                              void* d_out, int out_size)
{
    const float* r = (const float*)d_in[0];
    float* out = (float*)d_out;
    const int nrows = in_sizes[0] / NC;
    const int grid = (nrows + TPB - 1) / TPB;
    levinson_durbin_kernel<<<grid, TPB>>>(r, out, nrows);
}